// round 2
// baseline (speedup 1.0000x reference)
#include <cuda_runtime.h>
#include <cstdint>

#define NQ 6
#define DIM 64
#define NL 2
#define IN_DIM 4096
#define NH 32
#define B_TOTAL 32768

#define WARPS 16
#define THREADS 512
#define GRID 148
#define GROUPS (B_TOTAL / 2)

typedef unsigned long long u64;

// Precomputed by setup kernel:
//   g_MT[j][i] = M[i][j]  (the batch-independent circuit unitary, transposed, (re,im))
//   g_CT[i][h] = sum_w W_post[h][w] * SIGNS[w][i]
__device__ float2 g_MT[DIM][DIM];
__device__ float  g_CT[DIM][NH];

__device__ __forceinline__ float2 cmul(float2 a, float2 b) {
    return make_float2(a.x * b.x - a.y * b.y, a.x * b.y + a.y * b.x);
}
__device__ __forceinline__ float2 cadd(float2 a, float2 b) {
    return make_float2(a.x + b.x, a.y + b.y);
}

// ---------------------------------------------------------------------------
// Setup kernel: simulate the batch-independent part of the circuit on the 64
// basis states to build M, and fold W_post @ SIGNS into C. Cost ~ a few us.
// ---------------------------------------------------------------------------
__global__ void setup_kernel(const float* __restrict__ qw,
                             const float* __restrict__ Wpost) {
    __shared__ float2 st[DIM][DIM];  // st[column j][amplitude i]
    int j = threadIdx.x;
    if (j < DIM) {
        for (int i = 0; i < DIM; i++)
            st[j][i] = make_float2(i == j ? 1.f : 0.f, 0.f);
        for (int l = 0; l < NL; l++) {
            // Rot gates on each wire
            for (int w = 0; w < NQ; w++) {
                float phi = qw[(l * NQ + w) * 3 + 0];
                float th  = qw[(l * NQ + w) * 3 + 1];
                float om  = qw[(l * NQ + w) * 3 + 2];
                float ct = cosf(th * 0.5f), sn = sinf(th * 0.5f);
                float ap = (phi + om) * 0.5f, am = (phi - om) * 0.5f;
                float cap = cosf(ap), sap = sinf(ap);
                float cam = cosf(am), sam = sinf(am);
                float2 U00 = make_float2( ct * cap, -ct * sap);
                float2 U01 = make_float2(-sn * cam, -sn * sam);
                float2 U10 = make_float2( sn * cam, -sn * sam);
                float2 U11 = make_float2( ct * cap,  ct * sap);
                int mask = 1 << (NQ - 1 - w);  // wire w is the MSB-side bit
                for (int i0 = 0; i0 < DIM; i0++) {
                    if (i0 & mask) continue;
                    int i1 = i0 | mask;
                    float2 a0 = st[j][i0], a1 = st[j][i1];
                    st[j][i0] = cadd(cmul(U00, a0), cmul(U01, a1));
                    st[j][i1] = cadd(cmul(U10, a0), cmul(U11, a1));
                }
            }
            // CNOT ring: ctrl w -> tgt (w+r)%NQ, applied sequentially
            int r = l % (NQ - 1) + 1;
            for (int w = 0; w < NQ; w++) {
                int t = (w + r) % NQ;
                int mc = 1 << (NQ - 1 - w);
                int mt = 1 << (NQ - 1 - t);
                for (int i = 0; i < DIM; i++) {
                    if ((i & mc) && !(i & mt)) {
                        float2 tmp = st[j][i];
                        st[j][i] = st[j][i | mt];
                        st[j][i | mt] = tmp;
                    }
                }
            }
        }
        for (int i = 0; i < DIM; i++)
            g_MT[j][i] = st[j][i];  // column j, amplitude i == M[i][j]
    }
    // C = W_post @ SIGNS, stored [i][h]
    for (int idx = threadIdx.x; idx < DIM * NH; idx += blockDim.x) {
        int i = idx / NH, h = idx % NH;
        float s = 0.f;
        for (int w = 0; w < NQ; w++) {
            int bit = (i >> (NQ - 1 - w)) & 1;
            s += Wpost[h * NQ + w] * (1.f - 2.f * (float)bit);
        }
        g_CT[i][h] = s;
    }
}

// ---------------------------------------------------------------------------
// Packed f32x2 helpers (Blackwell dual-fp32 FMA path)
// ---------------------------------------------------------------------------
__device__ __forceinline__ u64 pack2(float lo, float hi) {
    u64 r;
    asm("mov.b64 %0, {%1, %2};" : "=l"(r) : "f"(lo), "f"(hi));
    return r;
}
__device__ __forceinline__ void unpack2(u64 v, float& lo, float& hi) {
    asm("mov.b64 {%0, %1}, %2;" : "=f"(lo), "=f"(hi) : "l"(v));
}
__device__ __forceinline__ void fma2(u64& d, u64 a, u64 b) {
    asm("fma.rn.f32x2 %0, %1, %2, %0;" : "+l"(d) : "l"(a), "l"(b));
}

// Shared memory layout (bytes):
//   Wsh  float[6*4096]            @      0   (98304)
//   Md   u64[64*64]   (MT dup)    @  98304   (32768)
//   CTd  u64[64*32]   (C dup'ed)  @ 131072   (16384)
//   buf  u64[WARPS*128]           @ 147456   (16384)
#define SMEM_BYTES (98304 + 32768 + 16384 + 16384)

__global__ void __launch_bounds__(THREADS, 1)
qag_main(const float* __restrict__ sv, const float* __restrict__ Wang,
         const float* __restrict__ bang, const float* __restrict__ bpost,
         float* __restrict__ out) {
    extern __shared__ __align__(16) char smem_raw[];
    float* Wsh  = (float*)smem_raw;
    u64*   Md   = (u64*)(smem_raw + 98304);
    u64*   CTd  = (u64*)(smem_raw + 131072);
    u64*   bufA = (u64*)(smem_raw + 147456);

    int tid  = threadIdx.x;
    int lane = tid & 31;
    int warp = tid >> 5;
    u64* wbuf = bufA + warp * 128;

    // Cooperative shared loads
    {
        const float4* Wg4 = (const float4*)Wang;
        float4* Wsh4 = (float4*)Wsh;
        for (int idx = tid; idx < NQ * IN_DIM / 4; idx += THREADS) Wsh4[idx] = Wg4[idx];
        const u64* Mg = (const u64*)g_MT;
        for (int idx = tid; idx < DIM * DIM; idx += THREADS) Md[idx] = Mg[idx];
        const float* Cg = (const float*)g_CT;
        for (int idx = tid; idx < DIM * NH; idx += THREADS) {
            float c = Cg[idx];
            CTd[idx] = pack2(c, c);
        }
    }
    __syncthreads();

    float ba[NQ];
#pragma unroll
    for (int w = 0; w < NQ; w++) ba[w] = bang[w];
    float bp = bpost[lane];

    for (int group = blockIdx.x * WARPS + warp; group < GROUPS;
         group += GRID * WARPS) {
        int rowA = group * 2, rowB = rowA + 1;
        const ulonglong2* pA = (const ulonglong2*)(sv + (size_t)rowA * IN_DIM);
        const ulonglong2* pB = (const ulonglong2*)(sv + (size_t)rowB * IN_DIM);

        // ---- Phase 1: angles GEMM (memory-bound). Warp covers 128 floats/iter.
        u64 accA[NQ], accB[NQ];
#pragma unroll
        for (int w = 0; w < NQ; w++) { accA[w] = 0ull; accB[w] = 0ull; }

#pragma unroll 4
        for (int k = 0; k < IN_DIM / 128; k++) {
            ulonglong2 a = pA[k * 32 + lane];
            ulonglong2 b = pB[k * 32 + lane];
#pragma unroll
            for (int w = 0; w < NQ; w++) {
                ulonglong2 wv =
                    *(const ulonglong2*)&Wsh[w * IN_DIM + k * 128 + lane * 4];
                fma2(accA[w], a.x, wv.x);
                fma2(accA[w], a.y, wv.y);
                fma2(accB[w], b.x, wv.x);
                fma2(accB[w], b.y, wv.y);
            }
        }

        // ---- Reduce partial dots across lanes; every lane gets all 6 angles.
        float cA[NQ], sA[NQ], cB[NQ], sB[NQ];
#pragma unroll
        for (int w = 0; w < NQ; w++) {
            float lo, hi;
            unpack2(accA[w], lo, hi);
            float vA = lo + hi;
            unpack2(accB[w], lo, hi);
            float vB = lo + hi;
#pragma unroll
            for (int off = 16; off; off >>= 1) {
                vA += __shfl_xor_sync(0xFFFFFFFFu, vA, off);
                vB += __shfl_xor_sync(0xFFFFFFFFu, vB, off);
            }
            float angA = (vA + ba[w]) * 0.5f;
            float angB = (vB + ba[w]) * 0.5f;
            cA[w] = __cosf(angA); sA[w] = __sinf(angA);
            cB[w] = __cosf(angB); sB[w] = __sinf(angB);
        }

        // ---- state0 product state: lane owns indices `lane` (wire0=0) and
        //      `lane+32` (wire0=1). Duplicate-pack for f32x2 matvec.
        float tA = 1.f, tB = 1.f;
#pragma unroll
        for (int w = 1; w < NQ; w++) {
            int bit = (lane >> (NQ - 1 - w)) & 1;
            tA *= bit ? sA[w] : cA[w];
            tB *= bit ? sB[w] : cB[w];
        }
        float e0A = cA[0] * tA, e1A = sA[0] * tA;
        float e0B = cB[0] * tB, e1B = sB[0] * tB;

        __syncwarp();
        wbuf[lane]          = pack2(e0A, e0A);
        wbuf[lane + 32]     = pack2(e1A, e1A);
        wbuf[64 + lane]     = pack2(e0B, e0B);
        wbuf[64 + lane + 32] = pack2(e1B, e1B);
        __syncwarp();

        // ---- Phase 2: complex matvec v = M @ s0 for both rows.
        //      acc = (re, im) packed; lane owns outputs i=lane, i=lane+32.
        u64 acc00 = 0ull, acc01 = 0ull, acc10 = 0ull, acc11 = 0ull;
#pragma unroll 4
        for (int jj = 0; jj < DIM; jj++) {
            u64 m0  = Md[jj * 64 + lane];
            u64 m1  = Md[jj * 64 + lane + 32];
            u64 sAd = wbuf[jj];        // broadcast
            u64 sBd = wbuf[64 + jj];   // broadcast
            fma2(acc00, m0, sAd);
            fma2(acc01, m1, sAd);
            fma2(acc10, m0, sBd);
            fma2(acc11, m1, sBd);
        }
        float re, im;
        unpack2(acc00, re, im); float p0A = re * re + im * im;
        unpack2(acc01, re, im); float p1A = re * re + im * im;
        unpack2(acc10, re, im); float p0B = re * re + im * im;
        unpack2(acc11, re, im); float p1B = re * re + im * im;

        // ---- probs into shared as (rowA, rowB) pairs
        __syncwarp();
        wbuf[lane]      = pack2(p0A, p0B);
        wbuf[lane + 32] = pack2(p1A, p1B);
        __syncwarp();

        // ---- Phase 3: logits = C @ probs + b_post; lane owns head h=lane,
        //      both rows in one f32x2 chain.
        u64 acc2 = pack2(bp, bp);
#pragma unroll 4
        for (int jj = 0; jj < DIM; jj++) {
            fma2(acc2, CTd[jj * NH + lane], wbuf[jj]);
        }
        float lA, lB;
        unpack2(acc2, lA, lB);
        out[(size_t)rowA * NH + lane] = 1.f + 0.5f * tanhf(lA);
        out[(size_t)rowB * NH + lane] = 1.f + 0.5f * tanhf(lB);
        __syncwarp();  // protect wbuf before next iteration's writes
    }
}

extern "C" void kernel_launch(void* const* d_in, const int* in_sizes, int n_in,
                              void* d_out, int out_size) {
    const float* sv    = (const float*)d_in[0];
    const float* Wang  = (const float*)d_in[1];
    const float* bang  = (const float*)d_in[2];
    const float* Wpost = (const float*)d_in[3];
    const float* bpost = (const float*)d_in[4];
    const float* qw    = (const float*)d_in[5];
    float* out = (float*)d_out;

    cudaFuncSetAttribute(qag_main, cudaFuncAttributeMaxDynamicSharedMemorySize,
                         SMEM_BYTES);
    setup_kernel<<<1, 128>>>(qw, Wpost);
    qag_main<<<GRID, THREADS, SMEM_BYTES>>>(sv, Wang, bang, bpost, out);
}

// round 3
// speedup vs baseline: 1.2974x; 1.2974x over previous
#include <cuda_runtime.h>

#define NQ 6
#define DIM 64
#define NL 2
#define IN_DIM 4096
#define NH 32
#define B_TOTAL 32768
#define GROUPS (B_TOTAL / 2)

#define THREADS 512
#define GRID 148
#define PAIRS_PER_BLOCK 111   // ceil(16384/148)
#define G 8                   // pairs per barrier period

typedef unsigned long long u64;

// Precomputed batch-independent circuit matrix (transposed) and folded C.
__device__ float2 g_MT[DIM][DIM];   // g_MT[j][i] = M[i][j] (re,im)
__device__ float  g_CT[DIM][NH];    // C[i][h] = sum_w Wpost[h][w]*SIGNS[w][i]

__device__ __forceinline__ float2 cmul(float2 a, float2 b) {
    return make_float2(a.x * b.x - a.y * b.y, a.x * b.y + a.y * b.x);
}
__device__ __forceinline__ float2 cadd(float2 a, float2 b) {
    return make_float2(a.x + b.x, a.y + b.y);
}

// ---------------------------------------------------------------------------
// Setup kernel — PARALLELIZED: each gate pass is 2048-4096 independent items
// across 512 threads, barrier between passes. ~3us instead of ~95us serial.
// ---------------------------------------------------------------------------
__global__ void setup_kernel(const float* __restrict__ qw,
                             const float* __restrict__ Wpost) {
    __shared__ float2 st[DIM * DIM];  // st[j*64 + i]
    int tid = threadIdx.x;
    for (int idx = tid; idx < DIM * DIM; idx += THREADS) {
        int j = idx >> 6, i = idx & 63;
        st[idx] = make_float2(i == j ? 1.f : 0.f, 0.f);
    }
    __syncthreads();
    for (int l = 0; l < NL; l++) {
        // Rot gates (different wires commute; apply each as a parallel pass)
        for (int w = 0; w < NQ; w++) {
            float phi = qw[(l * NQ + w) * 3 + 0];
            float th  = qw[(l * NQ + w) * 3 + 1];
            float om  = qw[(l * NQ + w) * 3 + 2];
            float ct = cosf(th * 0.5f), sn = sinf(th * 0.5f);
            float ap = (phi + om) * 0.5f, am = (phi - om) * 0.5f;
            float2 U00 = make_float2( ct * cosf(ap), -ct * sinf(ap));
            float2 U01 = make_float2(-sn * cosf(am), -sn * sinf(am));
            float2 U10 = make_float2( sn * cosf(am), -sn * sinf(am));
            float2 U11 = make_float2( ct * cosf(ap),  ct * sinf(ap));
            int mask = 1 << (NQ - 1 - w);
            for (int item = tid; item < DIM * 32; item += THREADS) {
                int j = item >> 5, p = item & 31;
                int low = p & (mask - 1);
                int i0 = ((p ^ low) << 1) | low;  // insert 0 bit at mask pos
                int i1 = i0 | mask;
                float2 a0 = st[j * 64 + i0], a1 = st[j * 64 + i1];
                st[j * 64 + i0] = cadd(cmul(U00, a0), cmul(U01, a1));
                st[j * 64 + i1] = cadd(cmul(U10, a0), cmul(U11, a1));
            }
            __syncthreads();
        }
        // CNOT ring, sequential gates, parallel within each gate
        int r = l % (NQ - 1) + 1;
        for (int w = 0; w < NQ; w++) {
            int t = (w + r) % NQ;
            int mc = 1 << (NQ - 1 - w), mt = 1 << (NQ - 1 - t);
            for (int idx = tid; idx < DIM * DIM; idx += THREADS) {
                int j = idx >> 6, i = idx & 63;
                if ((i & mc) && !(i & mt)) {
                    float2 tmp = st[j * 64 + i];
                    st[j * 64 + i] = st[j * 64 + (i | mt)];
                    st[j * 64 + (i | mt)] = tmp;
                }
            }
            __syncthreads();
        }
    }
    for (int idx = tid; idx < DIM * DIM; idx += THREADS)
        ((float2*)g_MT)[idx] = st[idx];
    for (int idx = tid; idx < DIM * NH; idx += THREADS) {
        int i = idx / NH, h = idx % NH;
        float s = 0.f;
        for (int w = 0; w < NQ; w++) {
            int bit = (i >> (NQ - 1 - w)) & 1;
            s += Wpost[h * NQ + w] * (1.f - 2.f * (float)bit);
        }
        g_CT[i][h] = s;
    }
}

// ---------------------------------------------------------------------------
// Packed f32x2 helpers
// ---------------------------------------------------------------------------
__device__ __forceinline__ u64 pack2(float lo, float hi) {
    u64 r;
    asm("mov.b64 %0, {%1, %2};" : "=l"(r) : "f"(lo), "f"(hi));
    return r;
}
__device__ __forceinline__ void unpack2(u64 v, float& lo, float& hi) {
    asm("mov.b64 {%0, %1}, %2;" : "=f"(lo), "=f"(hi) : "l"(v));
}
__device__ __forceinline__ void fma2(u64& d, u64 a, u64 b) {
    asm("fma.rn.f32x2 %0, %1, %2, %0;" : "+l"(d) : "l"(a), "l"(b));
}
__device__ __forceinline__ u64 add2(u64 a, u64 b) {
    u64 r;
    asm("add.rn.f32x2 %0, %1, %2;" : "=l"(r) : "l"(a), "l"(b));
    return r;
}

// Shared memory layout (bytes):
//   Md    u64[64*64]                @      0   (32768)
//   CTd   u64[64*32]                @  32768   (16384)
//   Pbuf  u64[2][G][6][128]         @  49152   (98304)
//   Cbuf  u64[16][128]              @ 147456   (16384)
#define SMEM_BYTES (32768 + 16384 + 98304 + 16384)

__global__ void __launch_bounds__(THREADS, 1)
qag_main(const float* __restrict__ sv, const float* __restrict__ Wang,
         const float* __restrict__ bang, const float* __restrict__ bpost,
         float* __restrict__ out) {
    extern __shared__ __align__(16) char smem_raw[];
    u64* Md   = (u64*)smem_raw;
    u64* CTd  = (u64*)(smem_raw + 32768);
    u64* Pbuf = (u64*)(smem_raw + 49152);
    u64* Cbuf = (u64*)(smem_raw + 147456);

    int tid  = threadIdx.x;
    int lane = tid & 31;
    int warp = tid >> 5;
    u64* wbuf = Cbuf + warp * 128;

    // Cooperative loads of the small constant matrices
    {
        const u64* Mg = (const u64*)g_MT;
        for (int idx = tid; idx < DIM * DIM; idx += THREADS) Md[idx] = Mg[idx];
        const float* Cg = (const float*)g_CT;
        for (int idx = tid; idx < DIM * NH; idx += THREADS) {
            float c = Cg[idx];
            CTd[idx] = pack2(c, c);
        }
    }

    // W_angles in registers: thread owns k in [tid*4, tid*4+4) and
    // [2048 + tid*4, ...+4). 24 u64 = 48 regs, 2 consecutive floats per u64.
    u64 Wr[NQ * 4];
    {
        const ulonglong2* W2 = (const ulonglong2*)Wang;
#pragma unroll
        for (int w = 0; w < NQ; w++) {
            ulonglong2 a = W2[w * 1024 + tid];
            ulonglong2 b = W2[w * 1024 + 512 + tid];
            Wr[w * 4 + 0] = a.x; Wr[w * 4 + 1] = a.y;
            Wr[w * 4 + 2] = b.x; Wr[w * 4 + 3] = b.y;
        }
    }

    float ba[NQ];
#pragma unroll
    for (int w = 0; w < NQ; w++) ba[w] = bang[w];
    float bp = bpost[lane];

    __syncthreads();

    int p0 = blockIdx.x * PAIRS_PER_BLOCK;
    int p1 = min(p0 + PAIRS_PER_BLOCK, GROUPS);
    int nper = (p1 - p0 + G - 1) / G;

    const ulonglong2* svb = (const ulonglong2*)sv;  // 1024 per row

    // Prefetch sv for pair p0 (always valid)
    ulonglong2 nA0, nA1, nB0, nB1;
    {
        size_t rA = (size_t)(2 * p0) * 1024;
        size_t rB = rA + 1024;
        nA0 = svb[rA + tid]; nA1 = svb[rA + 512 + tid];
        nB0 = svb[rB + tid]; nB1 = svb[rB + 512 + tid];
    }

    for (int j = 0; j < nper; j++) {
        int buf = j & 1;
#pragma unroll 1
        for (int t = 0; t < G; t++) {
            int pair = p0 + j * G + t;
            // current data
            ulonglong2 cA0 = nA0, cA1 = nA1, cB0 = nB0, cB1 = nB1;
            // issue next-pair loads early (in flight across compute/barrier)
            int np = pair + 1;
            if (np < p1) {
                size_t rA = (size_t)(2 * np) * 1024;
                size_t rB = rA + 1024;
                nA0 = svb[rA + tid]; nA1 = svb[rA + 512 + tid];
                nB0 = svb[rB + tid]; nB1 = svb[rB + 512 + tid];
            }
            if (pair < p1) {
                u64 accA[NQ], accB[NQ];
#pragma unroll
                for (int w = 0; w < NQ; w++) { accA[w] = 0ull; accB[w] = 0ull; }
#pragma unroll
                for (int w = 0; w < NQ; w++) {
                    fma2(accA[w], cA0.x, Wr[w * 4 + 0]);
                    fma2(accA[w], cA0.y, Wr[w * 4 + 1]);
                    fma2(accA[w], cA1.x, Wr[w * 4 + 2]);
                    fma2(accA[w], cA1.y, Wr[w * 4 + 3]);
                    fma2(accB[w], cB0.x, Wr[w * 4 + 0]);
                    fma2(accB[w], cB0.y, Wr[w * 4 + 1]);
                    fma2(accB[w], cB1.x, Wr[w * 4 + 2]);
                    fma2(accB[w], cB1.y, Wr[w * 4 + 3]);
                }
                float vA[NQ], vB[NQ];
#pragma unroll
                for (int w = 0; w < NQ; w++) {
                    float lo, hi;
                    unpack2(accA[w], lo, hi); vA[w] = lo + hi;
                    unpack2(accB[w], lo, hi); vB[w] = lo + hi;
                }
                // 2 butterfly rounds -> 8 distinct partials per warp
#pragma unroll
                for (int off = 16; off >= 8; off >>= 1) {
#pragma unroll
                    for (int w = 0; w < NQ; w++) {
                        vA[w] += __shfl_xor_sync(0xFFFFFFFFu, vA[w], off);
                        vB[w] += __shfl_xor_sync(0xFFFFFFFFu, vB[w], off);
                    }
                }
                if (lane < 8) {
                    u64* dst = Pbuf + (size_t)(buf * G + t) * 6 * 128;
#pragma unroll
                    for (int w = 0; w < NQ; w++)
                        dst[w * 128 + warp * 8 + lane] = pack2(vA[w], vB[w]);
                }
            }
        }
        __syncthreads();

        // Consumers: warps 0-7 on even periods, 8-15 on odd periods.
        int cw = warp - (buf ? 8 : 0);
        if (cw >= 0 && cw < G) {
            int pair = p0 + j * G + cw;
            if (pair < p1) {
                const u64* src = Pbuf + (size_t)(buf * G + cw) * 6 * 128;
                float cA[NQ], sA[NQ], cB[NQ], sB[NQ];
#pragma unroll
                for (int w = 0; w < NQ; w++) {
                    u64 s01 = add2(src[w * 128 + lane * 4 + 0],
                                   src[w * 128 + lane * 4 + 1]);
                    u64 s23 = add2(src[w * 128 + lane * 4 + 2],
                                   src[w * 128 + lane * 4 + 3]);
                    float a, b;
                    unpack2(add2(s01, s23), a, b);
#pragma unroll
                    for (int off = 16; off; off >>= 1) {
                        a += __shfl_xor_sync(0xFFFFFFFFu, a, off);
                        b += __shfl_xor_sync(0xFFFFFFFFu, b, off);
                    }
                    float angA = (a + ba[w]) * 0.5f;
                    float angB = (b + ba[w]) * 0.5f;
                    cA[w] = __cosf(angA); sA[w] = __sinf(angA);
                    cB[w] = __cosf(angB); sB[w] = __sinf(angB);
                }

                // Product state: lane owns amplitudes `lane` and `lane+32`
                float tA = 1.f, tB = 1.f;
#pragma unroll
                for (int w = 1; w < NQ; w++) {
                    int bit = (lane >> (NQ - 1 - w)) & 1;
                    tA *= bit ? sA[w] : cA[w];
                    tB *= bit ? sB[w] : cB[w];
                }
                float e0A = cA[0] * tA, e1A = sA[0] * tA;
                float e0B = cB[0] * tB, e1B = sB[0] * tB;

                __syncwarp();
                wbuf[lane]           = pack2(e0A, e0A);
                wbuf[lane + 32]      = pack2(e1A, e1A);
                wbuf[64 + lane]      = pack2(e0B, e0B);
                wbuf[64 + lane + 32] = pack2(e1B, e1B);
                __syncwarp();

                // Complex matvec v = M @ s0 for both rows (acc = (re,im))
                u64 acc00 = 0ull, acc01 = 0ull, acc10 = 0ull, acc11 = 0ull;
#pragma unroll 4
                for (int jj = 0; jj < DIM; jj++) {
                    u64 m0  = Md[jj * 64 + lane];
                    u64 m1  = Md[jj * 64 + lane + 32];
                    u64 sAd = wbuf[jj];
                    u64 sBd = wbuf[64 + jj];
                    fma2(acc00, m0, sAd);
                    fma2(acc01, m1, sAd);
                    fma2(acc10, m0, sBd);
                    fma2(acc11, m1, sBd);
                }
                float re, im;
                unpack2(acc00, re, im); float p0A = re * re + im * im;
                unpack2(acc01, re, im); float p1A = re * re + im * im;
                unpack2(acc10, re, im); float p0B = re * re + im * im;
                unpack2(acc11, re, im); float p1B = re * re + im * im;

                __syncwarp();
                wbuf[lane]      = pack2(p0A, p0B);
                wbuf[lane + 32] = pack2(p1A, p1B);
                __syncwarp();

                // logits = C @ probs + b_post; lane owns head h=lane
                u64 acc2 = pack2(bp, bp);
#pragma unroll 4
                for (int jj = 0; jj < DIM; jj++)
                    fma2(acc2, CTd[jj * NH + lane], wbuf[jj]);
                float lA, lB;
                unpack2(acc2, lA, lB);
                int rowA = 2 * pair, rowB = rowA + 1;
                out[(size_t)rowA * NH + lane] = 1.f + 0.5f * tanhf(lA);
                out[(size_t)rowB * NH + lane] = 1.f + 0.5f * tanhf(lB);
            }
        }
    }
}

extern "C" void kernel_launch(void* const* d_in, const int* in_sizes, int n_in,
                              void* d_out, int out_size) {
    const float* sv    = (const float*)d_in[0];
    const float* Wang  = (const float*)d_in[1];
    const float* bang  = (const float*)d_in[2];
    const float* Wpost = (const float*)d_in[3];
    const float* bpost = (const float*)d_in[4];
    const float* qw    = (const float*)d_in[5];
    float* out = (float*)d_out;

    cudaFuncSetAttribute(qag_main, cudaFuncAttributeMaxDynamicSharedMemorySize,
                         SMEM_BYTES);
    setup_kernel<<<1, THREADS>>>(qw, Wpost);
    qag_main<<<GRID, THREADS, SMEM_BYTES>>>(sv, Wang, bang, bpost, out);
}